// round 4
// baseline (speedup 1.0000x reference)
#include <cuda_runtime.h>

// entmax-1.5 attention, B=8, S=2048, D=128, fp32.
// One block = 16 query rows of one batch. Phases:
//   1) QK: z[16][2048] = 0.5 * Q K^T into SMEM (register-tiled 4q x 4k, K staged transposed)
//   2) bisection for tau per row, z held in registers (128 per thread), w written back to SMEM
//   3) PV: O = w V (register-tiled 4q x 4d, k-split by 2 with SMEM reduction)

#define SLEN 2048
#define DDIM 128
#define TQ   16
#define ZSTR 2052   // z row stride (floats), %4==0, rotates banks by 4 per row
#define KSTR 260    // transposed K tile row stride, %4==0
#define QTSTR 20    // transposed Q tile row stride, %4==0
#define NITER 40

__device__ __forceinline__ void fma4(float4& o, float s, const float4& v) {
    o.x += s * v.x; o.y += s * v.y; o.z += s * v.z; o.w += s * v.w;
}

__global__ __launch_bounds__(256, 1)
void entmax_attn_kernel(const float* __restrict__ Q,
                        const float* __restrict__ K,
                        const float* __restrict__ V,
                        float* __restrict__ O) {
    extern __shared__ float sm[];
    float* zsh = sm;                         // TQ * ZSTR floats
    float* ks  = sm + TQ * ZSTR;             // 32 * KSTR floats (reused as V stage: 64*128)
    float* qT  = ks + 32 * KSTR;             // 128 * QTSTR floats (reused as PV scratch)

    const int tid = threadIdx.x;
    const int b   = blockIdx.y;
    const int qt  = blockIdx.x;

    const float* Qb = Q + ((size_t)b * SLEN + qt * TQ) * DDIM;
    const float* Kb = K + (size_t)b * SLEN * DDIM;
    const float* Vb = V + (size_t)b * SLEN * DDIM;
    float*       Ob = O + ((size_t)b * SLEN + qt * TQ) * DDIM;

    // ---- stage Q tile transposed (qT[d][q]), pre-scaled by (alpha-1)=0.5 ----
    for (int i = tid; i < TQ * 32; i += 256) {
        int q  = i >> 5;
        int d4 = i & 31;
        float4 v = *(const float4*)(Qb + q * DDIM + d4 * 4);
        qT[(d4 * 4 + 0) * QTSTR + q] = 0.5f * v.x;
        qT[(d4 * 4 + 1) * QTSTR + q] = 0.5f * v.y;
        qT[(d4 * 4 + 2) * QTSTR + q] = 0.5f * v.z;
        qT[(d4 * 4 + 3) * QTSTR + q] = 0.5f * v.w;
    }

    // =========================== Phase 1: QK ===========================
    const int qg  = tid >> 6;   // 0..3   (4 query rows qg*4..qg*4+3)
    const int kg  = tid & 63;   // 0..63  (4 k cols kg*4..kg*4+3)
    const int ld4 = tid >> 5;   // warp id 0..7 -> d4 slot for K staging
    const int lk  = tid & 31;

    for (int kb = 0; kb < SLEN; kb += 256) {
        float4 a0 = {0,0,0,0}, a1 = {0,0,0,0}, a2 = {0,0,0,0}, a3 = {0,0,0,0};
        for (int db = 0; db < DDIM; db += 32) {
            __syncthreads();
            // stage K[kb..kb+255][db..db+31] transposed into ks[d][k] (conflict-free STS)
            #pragma unroll
            for (int r = 0; r < 8; r++) {
                int k = lk + r * 32;
                float4 v = *(const float4*)(Kb + (size_t)(kb + k) * DDIM + db + ld4 * 4);
                ks[(ld4 * 4 + 0) * KSTR + k] = v.x;
                ks[(ld4 * 4 + 1) * KSTR + k] = v.y;
                ks[(ld4 * 4 + 2) * KSTR + k] = v.z;
                ks[(ld4 * 4 + 3) * KSTR + k] = v.w;
            }
            __syncthreads();
            #pragma unroll
            for (int dd = 0; dd < 32; dd++) {
                float4 qv = *(const float4*)(qT + (db + dd) * QTSTR + qg * 4); // broadcast
                float4 kv = *(const float4*)(ks + dd * KSTR + kg * 4);         // contiguous
                fma4(a0, qv.x, kv);
                fma4(a1, qv.y, kv);
                fma4(a2, qv.z, kv);
                fma4(a3, qv.w, kv);
            }
        }
        *(float4*)(zsh + (qg * 4 + 0) * ZSTR + kb + kg * 4) = a0;
        *(float4*)(zsh + (qg * 4 + 1) * ZSTR + kb + kg * 4) = a1;
        *(float4*)(zsh + (qg * 4 + 2) * ZSTR + kb + kg * 4) = a2;
        *(float4*)(zsh + (qg * 4 + 3) * ZSTR + kb + kg * 4) = a3;
    }
    __syncthreads();

    // =========================== Phase 2: bisection ===========================
    {
        const int row    = tid >> 4;   // 0..15
        const int lane16 = tid & 15;   // 16 threads per row, within one warp
        float* zrow = zsh + row * ZSTR;

        float4 zr[32];
        #pragma unroll
        for (int j = 0; j < 32; j++)
            zr[j] = *(const float4*)(zrow + (j * 16 + lane16) * 4);

        float m = zr[0].x;
        #pragma unroll
        for (int j = 0; j < 32; j++)
            m = fmaxf(m, fmaxf(fmaxf(zr[j].x, zr[j].y), fmaxf(zr[j].z, zr[j].w)));
        #pragma unroll
        for (int o = 8; o >= 1; o >>= 1)
            m = fmaxf(m, __shfl_xor_sync(0xffffffffu, m, o, 16));

        float lo = m - 1.0f;
        float hi = m - 0.02209708691207961f;   // 2048^(1-1.5)
        float tau = 0.5f * (lo + hi);

        for (int it = 0; it < NITER; it++) {
            tau = 0.5f * (lo + hi);
            float s0 = 0.f, s1 = 0.f, s2 = 0.f, s3 = 0.f;
            #pragma unroll
            for (int j = 0; j < 32; j++) {
                float t0 = fmaxf(zr[j].x - tau, 0.f);
                float t1 = fmaxf(zr[j].y - tau, 0.f);
                float t2 = fmaxf(zr[j].z - tau, 0.f);
                float t3 = fmaxf(zr[j].w - tau, 0.f);
                s0 += t0 * t0; s1 += t1 * t1; s2 += t2 * t2; s3 += t3 * t3;
            }
            float s = (s0 + s1) + (s2 + s3);
            #pragma unroll
            for (int o = 8; o >= 1; o >>= 1)
                s += __shfl_xor_sync(0xffffffffu, s, o, 16);
            if (s >= 1.0f) lo = tau; else hi = tau;
        }

        // final p, Z with last tau (matches reference exactly)
        float s0 = 0.f, s1 = 0.f, s2 = 0.f, s3 = 0.f;
        #pragma unroll
        for (int j = 0; j < 32; j++) {
            float4 p;
            p.x = fmaxf(zr[j].x - tau, 0.f); p.x *= p.x;
            p.y = fmaxf(zr[j].y - tau, 0.f); p.y *= p.y;
            p.z = fmaxf(zr[j].z - tau, 0.f); p.z *= p.z;
            p.w = fmaxf(zr[j].w - tau, 0.f); p.w *= p.w;
            s0 += p.x; s1 += p.y; s2 += p.z; s3 += p.w;
            zr[j] = p;
        }
        float Zs = (s0 + s1) + (s2 + s3);
        #pragma unroll
        for (int o = 8; o >= 1; o >>= 1)
            Zs += __shfl_xor_sync(0xffffffffu, Zs, o, 16);
        float invZ = 1.0f / Zs;

        #pragma unroll
        for (int j = 0; j < 32; j++) {
            float4 w;
            w.x = zr[j].x * invZ; w.y = zr[j].y * invZ;
            w.z = zr[j].z * invZ; w.w = zr[j].w * invZ;
            *(float4*)(zrow + (j * 16 + lane16) * 4) = w;
        }
    }
    __syncthreads();

    // =========================== Phase 3: PV ===========================
    {
        float* vs = ks;        // reuse: 64 x 128 floats
        const int kpart = (tid >> 5) & 1;  // constant per warp
        const int dg    = tid & 31;        // d4 group, lane index

        float4 o0 = {0,0,0,0}, o1 = {0,0,0,0}, o2 = {0,0,0,0}, o3 = {0,0,0,0};

        for (int vb = 0; vb < SLEN; vb += 64) {
            __syncthreads();
            for (int i = tid; i < 64 * 32; i += 256)
                ((float4*)vs)[i] = *(const float4*)(Vb + (size_t)vb * DDIM + i * 4);
            __syncthreads();

            #pragma unroll
            for (int g = 0; g < 8; g++) {
                int k0 = (2 * g + kpart) * 4;
                const float* zp = zsh + vb + k0;
                float4 w0 = *(const float4*)(zp + (qg * 4 + 0) * ZSTR);
                float4 w1 = *(const float4*)(zp + (qg * 4 + 1) * ZSTR);
                float4 w2 = *(const float4*)(zp + (qg * 4 + 2) * ZSTR);
                float4 w3 = *(const float4*)(zp + (qg * 4 + 3) * ZSTR);
                float4 v0 = *(const float4*)(vs + (k0 + 0) * DDIM + dg * 4);
                float4 v1 = *(const float4*)(vs + (k0 + 1) * DDIM + dg * 4);
                float4 v2 = *(const float4*)(vs + (k0 + 2) * DDIM + dg * 4);
                float4 v3 = *(const float4*)(vs + (k0 + 3) * DDIM + dg * 4);
                fma4(o0, w0.x, v0); fma4(o0, w0.y, v1); fma4(o0, w0.z, v2); fma4(o0, w0.w, v3);
                fma4(o1, w1.x, v0); fma4(o1, w1.y, v1); fma4(o1, w1.z, v2); fma4(o1, w1.w, v3);
                fma4(o2, w2.x, v0); fma4(o2, w2.y, v1); fma4(o2, w2.z, v2); fma4(o2, w2.w, v3);
                fma4(o3, w3.x, v0); fma4(o3, w3.y, v1); fma4(o3, w3.z, v2); fma4(o3, w3.w, v3);
            }
        }

        // reduce the two k-partitions via SMEM scratch (reuse qT region)
        float* scratch = qT;
        const int pos = qg * 32 + dg;   // 0..127
        __syncthreads();
        if (kpart == 1) {
            *(float4*)(scratch + pos * 20 + 0)  = o0;
            *(float4*)(scratch + pos * 20 + 4)  = o1;
            *(float4*)(scratch + pos * 20 + 8)  = o2;
            *(float4*)(scratch + pos * 20 + 12) = o3;
        }
        __syncthreads();
        if (kpart == 0) {
            float4 p0 = *(const float4*)(scratch + pos * 20 + 0);
            float4 p1 = *(const float4*)(scratch + pos * 20 + 4);
            float4 p2 = *(const float4*)(scratch + pos * 20 + 8);
            float4 p3 = *(const float4*)(scratch + pos * 20 + 12);
            o0.x += p0.x; o0.y += p0.y; o0.z += p0.z; o0.w += p0.w;
            o1.x += p1.x; o1.y += p1.y; o1.z += p1.z; o1.w += p1.w;
            o2.x += p2.x; o2.y += p2.y; o2.z += p2.z; o2.w += p2.w;
            o3.x += p3.x; o3.y += p3.y; o3.z += p3.z; o3.w += p3.w;
            *(float4*)(Ob + (qg * 4 + 0) * DDIM + dg * 4) = o0;
            *(float4*)(Ob + (qg * 4 + 1) * DDIM + dg * 4) = o1;
            *(float4*)(Ob + (qg * 4 + 2) * DDIM + dg * 4) = o2;
            *(float4*)(Ob + (qg * 4 + 3) * DDIM + dg * 4) = o3;
        }
    }
}

extern "C" void kernel_launch(void* const* d_in, const int* in_sizes, int n_in,
                              void* d_out, int out_size) {
    const float* Q = (const float*)d_in[0];
    const float* K = (const float*)d_in[1];
    const float* V = (const float*)d_in[2];
    float* O = (float*)d_out;

    const int B = in_sizes[0] / (SLEN * DDIM);   // 8
    const size_t smem = (size_t)(TQ * ZSTR + 32 * KSTR + 128 * QTSTR) * sizeof(float); // 174,848 B

    cudaFuncSetAttribute(entmax_attn_kernel,
                         cudaFuncAttributeMaxDynamicSharedMemorySize, (int)smem);

    dim3 grid(SLEN / TQ, B);
    entmax_attn_kernel<<<grid, 256, smem>>>(Q, K, V, O);
}

// round 8
// speedup vs baseline: 1.0878x; 1.0878x over previous
#include <cuda_runtime.h>

// entmax-1.5 attention, B=8, S=2048, D=128, fp32.
// One block = 16 query rows of one batch, 512 threads (16 warps).
//   1) QK: z[16][2048] = 0.5 * Q K^T into SMEM (4q x 4k register tile, K staged transposed)
//   2) bisection for tau: one warp per row, 64 z-values/thread in registers
//   3) PV: O = w V (4q x 4d register tile, 4-way k-split + SMEM reduction)

#define SLEN 2048
#define DDIM 128
#define TQ   16
#define ZSTR 2052   // z row stride (floats)
#define KSTR 260    // transposed K tile row stride (floats)
#define QTSTR 20    // transposed Q tile row stride (floats)
#define NITER 28
#define NTHR 512

__device__ __forceinline__ void fma4(float4& o, float s, const float4& v) {
    o.x += s * v.x; o.y += s * v.y; o.z += s * v.z; o.w += s * v.w;
}

__global__ __launch_bounds__(NTHR, 1)
void entmax_attn_kernel(const float* __restrict__ Q,
                        const float* __restrict__ K,
                        const float* __restrict__ V,
                        float* __restrict__ O) {
    extern __shared__ float sm[];
    float* zsh = sm;                         // TQ * ZSTR
    float* ks  = sm + TQ * ZSTR;             // 32 * KSTR (reused as V stage 64*128 and PV scratch)
    float* qT  = ks + 32 * KSTR;             // 128 * QTSTR

    const int tid = threadIdx.x;
    const int b   = blockIdx.y;
    const int qt  = blockIdx.x;

    const float* Qb = Q + ((size_t)b * SLEN + qt * TQ) * DDIM;
    const float* Kb = K + (size_t)b * SLEN * DDIM;
    const float* Vb = V + (size_t)b * SLEN * DDIM;
    float*       Ob = O + ((size_t)b * SLEN + qt * TQ) * DDIM;

    // ---- stage Q tile transposed qT[d][q], pre-scaled by (alpha-1)=0.5 ----
    {
        int q  = tid >> 5;       // 0..15
        int d4 = tid & 31;       // 0..31
        float4 v = *(const float4*)(Qb + q * DDIM + d4 * 4);
        qT[(d4 * 4 + 0) * QTSTR + q] = 0.5f * v.x;
        qT[(d4 * 4 + 1) * QTSTR + q] = 0.5f * v.y;
        qT[(d4 * 4 + 2) * QTSTR + q] = 0.5f * v.z;
        qT[(d4 * 4 + 3) * QTSTR + q] = 0.5f * v.w;
    }

    // =========================== Phase 1: QK ===========================
    const int qg  = tid >> 7;    // 0..3  (query rows qg*4..qg*4+3)
    const int kg  = tid & 127;   // 0..127 (k cols kg*4..kg*4+3)
    const int ld4 = tid >> 6;    // 0..7   (d4 slot for K staging)
    const int lk  = tid & 63;

    for (int kb = 0; kb < SLEN; kb += 512) {
        float4 a0 = {0,0,0,0}, a1 = {0,0,0,0}, a2 = {0,0,0,0}, a3 = {0,0,0,0};
        for (int db = 0; db < DDIM; db += 32) {
            __syncthreads();
            // stage K[kb..kb+511? no: kb..kb+255][..] -> wait, 512 k per kb, stage in two halves
            // stage K[kb..kb+511][db..db+31] transposed: 512k x 32d = 4096 float4; 512 thr -> 8 each
            #pragma unroll
            for (int r = 0; r < 8; r++) {
                int k = lk + r * 64;
                // two half-tiles: k in [0,512); ks holds only 512? KSTR row holds 512? No: KSTR=260.
                // -> stage into two d-slices is wrong; instead stage 256k at a time:
                // handled below
                (void)k;
            }
            // (real staging below)
            break;
        }
        // --- real loop: process 512 k in two 256-k sub-tiles to fit ks (32 x 260) ---
        for (int half = 0; half < 2; half++) {
            int kbase = kb + half * 256;
            float4* acc0 = half ? &a2 : &a0;   // placeholder, not used
            (void)acc0; (void)kbase;
        }
        // NOTE: restructured below — see phase1_real
        (void)a0; (void)a1; (void)a2; (void)a3;
        break;
    }

    // ---- phase 1 (real): iterate kb in steps of 256, each thread owns 4q x 2k ----
    // 512 threads: qg2 = tid>>7 (4 q rows), kg2 = tid&127 -> k cols kg2*2..kg2*2+1
    {
        const int kg2 = tid & 127;
        for (int kb = 0; kb < SLEN; kb += 256) {
            float2 c0 = {0,0}, c1 = {0,0}, c2 = {0,0}, c3 = {0,0};
            for (int db = 0; db < DDIM; db += 32) {
                __syncthreads();
                #pragma unroll
                for (int r = 0; r < 4; r++) {
                    int k = lk + r * 64;
                    float4 v = *(const float4*)(Kb + (size_t)(kb + k) * DDIM + db + ld4 * 4);
                    ks[(ld4 * 4 + 0) * KSTR + k] = v.x;
                    ks[(ld4 * 4 + 1) * KSTR + k] = v.y;
                    ks[(ld4 * 4 + 2) * KSTR + k] = v.z;
                    ks[(ld4 * 4 + 3) * KSTR + k] = v.w;
                }
                __syncthreads();
                #pragma unroll
                for (int dd = 0; dd < 32; dd++) {
                    float4 qv = *(const float4*)(qT + (db + dd) * QTSTR + qg * 4); // broadcast
                    float2 kv = *(const float2*)(ks + dd * KSTR + kg2 * 2);        // contiguous
                    c0.x += qv.x * kv.x; c0.y += qv.x * kv.y;
                    c1.x += qv.y * kv.x; c1.y += qv.y * kv.y;
                    c2.x += qv.z * kv.x; c2.y += qv.z * kv.y;
                    c3.x += qv.w * kv.x; c3.y += qv.w * kv.y;
                }
            }
            *(float2*)(zsh + (qg * 4 + 0) * ZSTR + kb + kg2 * 2) = c0;
            *(float2*)(zsh + (qg * 4 + 1) * ZSTR + kb + kg2 * 2) = c1;
            *(float2*)(zsh + (qg * 4 + 2) * ZSTR + kb + kg2 * 2) = c2;
            *(float2*)(zsh + (qg * 4 + 3) * ZSTR + kb + kg2 * 2) = c3;
        }
    }
    __syncthreads();

    // =========================== Phase 2: bisection (one warp per row) ===========================
    {
        const int row  = tid >> 5;   // 0..15
        const int lane = tid & 31;
        float* zrow = zsh + row * ZSTR;

        float4 zr[16];
        #pragma unroll
        for (int j = 0; j < 16; j++)
            zr[j] = *(const float4*)(zrow + (j * 32 + lane) * 4);

        float m = zr[0].x;
        #pragma unroll
        for (int j = 0; j < 16; j++)
            m = fmaxf(m, fmaxf(fmaxf(zr[j].x, zr[j].y), fmaxf(zr[j].z, zr[j].w)));
        #pragma unroll
        for (int o = 16; o >= 1; o >>= 1)
            m = fmaxf(m, __shfl_xor_sync(0xffffffffu, m, o));

        float lo = m - 1.0f;
        float hi = m - 0.02209708691207961f;   // 2048^(1-1.5)
        float tau = 0.5f * (lo + hi);

        for (int it = 0; it < NITER; it++) {
            tau = 0.5f * (lo + hi);
            float s0 = 0.f, s1 = 0.f, s2 = 0.f, s3 = 0.f;
            #pragma unroll
            for (int j = 0; j < 16; j++) {
                float t0 = fmaxf(zr[j].x - tau, 0.f);
                float t1 = fmaxf(zr[j].y - tau, 0.f);
                float t2 = fmaxf(zr[j].z - tau, 0.f);
                float t3 = fmaxf(zr[j].w - tau, 0.f);
                s0 += t0 * t0; s1 += t1 * t1; s2 += t2 * t2; s3 += t3 * t3;
            }
            float s = (s0 + s1) + (s2 + s3);
            #pragma unroll
            for (int o = 16; o >= 1; o >>= 1)
                s += __shfl_xor_sync(0xffffffffu, s, o);
            if (s >= 1.0f) lo = tau; else hi = tau;
        }

        // final p, Z with last tau (matches reference)
        float s0 = 0.f, s1 = 0.f, s2 = 0.f, s3 = 0.f;
        #pragma unroll
        for (int j = 0; j < 16; j++) {
            float4 p;
            p.x = fmaxf(zr[j].x - tau, 0.f); p.x *= p.x;
            p.y = fmaxf(zr[j].y - tau, 0.f); p.y *= p.y;
            p.z = fmaxf(zr[j].z - tau, 0.f); p.z *= p.z;
            p.w = fmaxf(zr[j].w - tau, 0.f); p.w *= p.w;
            s0 += p.x; s1 += p.y; s2 += p.z; s3 += p.w;
            zr[j] = p;
        }
        float Zs = (s0 + s1) + (s2 + s3);
        #pragma unroll
        for (int o = 16; o >= 1; o >>= 1)
            Zs += __shfl_xor_sync(0xffffffffu, Zs, o);
        float invZ = 1.0f / Zs;

        #pragma unroll
        for (int j = 0; j < 16; j++) {
            float4 w;
            w.x = zr[j].x * invZ; w.y = zr[j].y * invZ;
            w.z = zr[j].z * invZ; w.w = zr[j].w * invZ;
            *(float4*)(zrow + (j * 32 + lane) * 4) = w;
        }
    }
    __syncthreads();

    // =========================== Phase 3: PV ===========================
    {
        float* vs = ks;                    // reuse: 64 x 128 floats
        const int kpart = (tid >> 5) & 3;  // 0..3, constant per warp
        const int dg    = tid & 31;

        float4 o0 = {0,0,0,0}, o1 = {0,0,0,0}, o2 = {0,0,0,0}, o3 = {0,0,0,0};

        for (int vb = 0; vb < SLEN; vb += 64) {
            __syncthreads();
            #pragma unroll
            for (int r = 0; r < 4; r++)
                ((float4*)vs)[tid + r * 512] =
                    *(const float4*)(Vb + (size_t)vb * DDIM + (tid + r * 512) * 4);
            __syncthreads();

            #pragma unroll
            for (int g = 0; g < 4; g++) {
                int k0 = (g * 4 + kpart) * 4;
                const float* zp = zsh + vb + k0;
                float4 w0 = *(const float4*)(zp + (qg * 4 + 0) * ZSTR);  // broadcast
                float4 w1 = *(const float4*)(zp + (qg * 4 + 1) * ZSTR);
                float4 w2 = *(const float4*)(zp + (qg * 4 + 2) * ZSTR);
                float4 w3 = *(const float4*)(zp + (qg * 4 + 3) * ZSTR);
                float4 v0 = *(const float4*)(vs + (k0 + 0) * DDIM + dg * 4);
                float4 v1 = *(const float4*)(vs + (k0 + 1) * DDIM + dg * 4);
                float4 v2 = *(const float4*)(vs + (k0 + 2) * DDIM + dg * 4);
                float4 v3 = *(const float4*)(vs + (k0 + 3) * DDIM + dg * 4);
                fma4(o0, w0.x, v0); fma4(o0, w0.y, v1); fma4(o0, w0.z, v2); fma4(o0, w0.w, v3);
                fma4(o1, w1.x, v0); fma4(o1, w1.y, v1); fma4(o1, w1.z, v2); fma4(o1, w1.w, v3);
                fma4(o2, w2.x, v0); fma4(o2, w2.y, v1); fma4(o2, w2.z, v2); fma4(o2, w2.w, v3);
                fma4(o3, w3.x, v0); fma4(o3, w3.y, v1); fma4(o3, w3.z, v2); fma4(o3, w3.w, v3);
            }
        }

        // reduce 4 k-partitions: parts 1..3 store to scratch, part 0 accumulates
        float* scratch = vs;               // 8192 floats available; need 3*128*20 = 7680
        const int pos = qg * 32 + dg;      // 0..127
        __syncthreads();
        if (kpart != 0) {
            float* sp = scratch + ((kpart - 1) * 128 + pos) * 20;
            *(float4*)(sp + 0)  = o0;
            *(float4*)(sp + 4)  = o1;
            *(float4*)(sp + 8)  = o2;
            *(float4*)(sp + 12) = o3;
        }
        __syncthreads();
        if (kpart == 0) {
            #pragma unroll
            for (int p = 0; p < 3; p++) {
                const float* sp = scratch + (p * 128 + pos) * 20;
                float4 p0 = *(const float4*)(sp + 0);
                float4 p1 = *(const float4*)(sp + 4);
                float4 p2 = *(const float4*)(sp + 8);
                float4 p3 = *(const float4*)(sp + 12);
                o0.x += p0.x; o0.y += p0.y; o0.z += p0.z; o0.w += p0.w;
                o1.x += p1.x; o1.y += p1.y; o1.z += p1.z; o1.w += p1.w;
                o2.x += p2.x; o2.y += p2.y; o2.z += p2.z; o2.w += p2.w;
                o3.x += p3.x; o3.y += p3.y; o3.z += p3.z; o3.w += p3.w;
            }
            *(float4*)(Ob + (qg * 4 + 0) * DDIM + dg * 4) = o0;
            *(float4*)(Ob + (qg * 4 + 1) * DDIM + dg * 4) = o1;
            *(float4*)(Ob + (qg * 4 + 2) * DDIM + dg * 4) = o2;
            *(float4*)(Ob + (qg * 4 + 3) * DDIM + dg * 4) = o3;
        }
    }
}

extern "C" void kernel_launch(void* const* d_in, const int* in_sizes, int n_in,
                              void* d_out, int out_size) {
    const float* Q = (const float*)d_in[0];
    const float* K = (const float*)d_in[1];
    const float* V = (const float*)d_in[2];
    float* O = (float*)d_out;

    const int B = in_sizes[0] / (SLEN * DDIM);   // 8
    const size_t smem = (size_t)(TQ * ZSTR + 32 * KSTR + 128 * QTSTR) * sizeof(float); // 174,848 B

    cudaFuncSetAttribute(entmax_attn_kernel,
                         cudaFuncAttributeMaxDynamicSharedMemorySize, (int)smem);

    dim3 grid(SLEN / TQ, B);
    entmax_attn_kernel<<<grid, NTHR, smem>>>(Q, K, V, O);
}

// round 11
// speedup vs baseline: 1.6473x; 1.5143x over previous
#include <cuda_runtime.h>

// entmax-1.5 attention, B=8, S=2048, D=128, fp32.
// One block = 16 query rows of one batch, 512 threads (16 warps).
//   1) QK: z[16][2048] = 0.5*Q K^T in SMEM. 4q x 4k register tile, 512-k K tile
//      staged transposed with coalesced LDG (8 lanes per K-row 128B slice; 4 full
//      lines per warp-LDG) and an XOR swizzle (k' = k ^ (4*(dRow>>2))) making both
//      the transposed STS and the compute LDS conflict-free.
//   2) bisection for tau: one warp per row, 64 z-values/thread in registers,
//      full-warp shfl reductions. 22 iters (bracket < fp32 ulp of tau).
//   3) PV: O = w V. 8q x 4d register tile, 8-way k-split, 128-k V tiles,
//      3-stage conflict-free SMEM tree reduction.

#define SLEN 2048
#define DDIM 128
#define TQ   16
#define ZSTR 2052   // z row stride (floats)
#define KSTR2 516   // transposed K tile row stride (floats), 512 k + pad
#define QTSTR 20    // transposed Q tile row stride (floats)
#define NITER 22
#define NTHR 512

__device__ __forceinline__ void fma4(float4& o, float s, const float4& v) {
    o.x += s * v.x; o.y += s * v.y; o.z += s * v.z; o.w += s * v.w;
}
__device__ __forceinline__ void add4(float4& o, const float4& v) {
    o.x += v.x; o.y += v.y; o.z += v.z; o.w += v.w;
}

__global__ __launch_bounds__(NTHR, 1)
void entmax_attn_kernel(const float* __restrict__ Q,
                        const float* __restrict__ K,
                        const float* __restrict__ V,
                        float* __restrict__ O) {
    extern __shared__ float sm[];
    float* zsh = sm;                          // 16 * 2052 = 32,832 floats
    float* ks  = sm + TQ * ZSTR;              // 32 * 516  = 16,512 floats (reused: V stage / reduction)
    float* qT  = ks + 32 * KSTR2;             // 128 * 20  =  2,560 floats

    const int tid  = threadIdx.x;
    const int lane = tid & 31;
    const int warp = tid >> 5;
    const int b    = blockIdx.y;
    const int qt   = blockIdx.x;

    const float* Qb = Q + ((size_t)b * SLEN + qt * TQ) * DDIM;
    const float* Kb = K + (size_t)b * SLEN * DDIM;
    const float* Vb = V + (size_t)b * SLEN * DDIM;
    float*       Ob = O + ((size_t)b * SLEN + qt * TQ) * DDIM;

    // ---- stage Q tile transposed qT[d][q], pre-scaled by (alpha-1)=0.5 ----
    {
        int q  = tid >> 5;       // 0..15
        int d4 = tid & 31;       // 0..31
        float4 v = *(const float4*)(Qb + q * DDIM + d4 * 4);
        qT[(d4 * 4 + 0) * QTSTR + q] = 0.5f * v.x;
        qT[(d4 * 4 + 1) * QTSTR + q] = 0.5f * v.y;
        qT[(d4 * 4 + 2) * QTSTR + q] = 0.5f * v.z;
        qT[(d4 * 4 + 3) * QTSTR + q] = 0.5f * v.w;
    }

    // =========================== Phase 1: QK ===========================
    // 4q x 4k per thread: qg = tid>>7 (4 q rows), kg4 = (tid&127)*4 (4 k cols).
    const int qg  = tid >> 7;
    const int kg4 = (tid & 127) * 4;
    // staging: 8 lanes cover one K-row 128B slice; 4 rows per warp-LDG (fully coalesced).
    const int d16  = (lane & 7) * 4;   // d chunk start within 32-float slice
    const int ksub = lane >> 3;        // 0..3

    for (int kb = 0; kb < SLEN; kb += 512) {
        float4 a0 = {0,0,0,0}, a1 = {0,0,0,0}, a2 = {0,0,0,0}, a3 = {0,0,0,0};
        for (int db = 0; db < DDIM; db += 32) {
            __syncthreads();
            #pragma unroll
            for (int r = 0; r < 8; r++) {
                int k = warp * 32 + r * 4 + ksub;           // contiguous 32 k per warp
                float4 v = *(const float4*)(Kb + (size_t)(kb + k) * DDIM + db + d16);
                int kx = k ^ d16;                            // swizzle (stays in warp's 32-k window)
                ks[(d16 + 0) * KSTR2 + kx] = v.x;
                ks[(d16 + 1) * KSTR2 + kx] = v.y;
                ks[(d16 + 2) * KSTR2 + kx] = v.z;
                ks[(d16 + 3) * KSTR2 + kx] = v.w;
            }
            __syncthreads();
            #pragma unroll
            for (int dd = 0; dd < 32; dd++) {
                int f = dd & 0x1C;                           // 4*(dd>>2), warp-uniform
                float4 qv = *(const float4*)(qT + (db + dd) * QTSTR + qg * 4);   // broadcast
                float4 kv = *(const float4*)(ks + dd * KSTR2 + (kg4 ^ f));       // conflict-free
                fma4(a0, qv.x, kv);
                fma4(a1, qv.y, kv);
                fma4(a2, qv.z, kv);
                fma4(a3, qv.w, kv);
            }
        }
        *(float4*)(zsh + (qg * 4 + 0) * ZSTR + kb + kg4) = a0;
        *(float4*)(zsh + (qg * 4 + 1) * ZSTR + kb + kg4) = a1;
        *(float4*)(zsh + (qg * 4 + 2) * ZSTR + kb + kg4) = a2;
        *(float4*)(zsh + (qg * 4 + 3) * ZSTR + kb + kg4) = a3;
    }
    __syncthreads();

    // =========================== Phase 2: bisection (one warp per row) ===========================
    {
        const int row = warp;      // 0..15
        float* zrow = zsh + row * ZSTR;

        float4 zr[16];
        #pragma unroll
        for (int j = 0; j < 16; j++)
            zr[j] = *(const float4*)(zrow + (j * 32 + lane) * 4);

        float m = zr[0].x;
        #pragma unroll
        for (int j = 0; j < 16; j++)
            m = fmaxf(m, fmaxf(fmaxf(zr[j].x, zr[j].y), fmaxf(zr[j].z, zr[j].w)));
        #pragma unroll
        for (int o = 16; o >= 1; o >>= 1)
            m = fmaxf(m, __shfl_xor_sync(0xffffffffu, m, o));

        float lo = m - 1.0f;
        float hi = m - 0.02209708691207961f;   // 2048^(1-1.5)
        float tau = 0.5f * (lo + hi);

        for (int it = 0; it < NITER; it++) {
            tau = 0.5f * (lo + hi);
            float s0 = 0.f, s1 = 0.f, s2 = 0.f, s3 = 0.f;
            #pragma unroll
            for (int j = 0; j < 16; j++) {
                float t0 = fmaxf(zr[j].x - tau, 0.f);
                float t1 = fmaxf(zr[j].y - tau, 0.f);
                float t2 = fmaxf(zr[j].z - tau, 0.f);
                float t3 = fmaxf(zr[j].w - tau, 0.f);
                s0 += t0 * t0; s1 += t1 * t1; s2 += t2 * t2; s3 += t3 * t3;
            }
            float s = (s0 + s1) + (s2 + s3);
            #pragma unroll
            for (int o = 16; o >= 1; o >>= 1)
                s += __shfl_xor_sync(0xffffffffu, s, o);
            if (s >= 1.0f) lo = tau; else hi = tau;
        }

        // final p, Z with last tau (matches reference)
        float s0 = 0.f, s1 = 0.f, s2 = 0.f, s3 = 0.f;
        #pragma unroll
        for (int j = 0; j < 16; j++) {
            float4 p;
            p.x = fmaxf(zr[j].x - tau, 0.f); p.x *= p.x;
            p.y = fmaxf(zr[j].y - tau, 0.f); p.y *= p.y;
            p.z = fmaxf(zr[j].z - tau, 0.f); p.z *= p.z;
            p.w = fmaxf(zr[j].w - tau, 0.f); p.w *= p.w;
            s0 += p.x; s1 += p.y; s2 += p.z; s3 += p.w;
            zr[j] = p;
        }
        float Zs = (s0 + s1) + (s2 + s3);
        #pragma unroll
        for (int o = 16; o >= 1; o >>= 1)
            Zs += __shfl_xor_sync(0xffffffffu, Zs, o);
        float invZ = 1.0f / Zs;

        #pragma unroll
        for (int j = 0; j < 16; j++) {
            float4 w;
            w.x = zr[j].x * invZ; w.y = zr[j].y * invZ;
            w.z = zr[j].z * invZ; w.w = zr[j].w * invZ;
            *(float4*)(zrow + (j * 32 + lane) * 4) = w;
        }
    }
    __syncthreads();

    // =========================== Phase 3: PV ===========================
    {
        float* vs = ks;                    // reuse: 128 x 128 floats = 16384 (fits in 16512)
        const int qg3   = warp >> 3;       // 0..1 -> 8 q rows each
        const int kpart = warp & 7;        // 0..7, warp-constant
        const int dg    = lane;            // 0..31 -> 4 d cols

        float4 o[8];
        #pragma unroll
        for (int qi = 0; qi < 8; qi++) o[qi] = make_float4(0.f, 0.f, 0.f, 0.f);

        for (int vb = 0; vb < SLEN; vb += 128) {
            __syncthreads();
            #pragma unroll
            for (int r = 0; r < 8; r++)
                ((float4*)vs)[tid + r * 512] =
                    *(const float4*)(Vb + (size_t)vb * DDIM + (tid + r * 512) * 4);
            __syncthreads();

            #pragma unroll
            for (int g = 0; g < 4; g++) {
                int k0 = (g * 8 + kpart) * 4;
                const float* zp = zsh + vb + k0;
                float4 v0 = *(const float4*)(vs + (k0 + 0) * DDIM + dg * 4);
                float4 v1 = *(const float4*)(vs + (k0 + 1) * DDIM + dg * 4);
                float4 v2 = *(const float4*)(vs + (k0 + 2) * DDIM + dg * 4);
                float4 v3 = *(const float4*)(vs + (k0 + 3) * DDIM + dg * 4);
                #pragma unroll
                for (int qi = 0; qi < 8; qi++) {
                    float4 w = *(const float4*)(zp + (qg3 * 8 + qi) * ZSTR);  // broadcast
                    fma4(o[qi], w.x, v0); fma4(o[qi], w.y, v1);
                    fma4(o[qi], w.z, v2); fma4(o[qi], w.w, v3);
                }
            }
        }

        // ---- 3-stage tree reduction of 8 k-partitions via SMEM (float4 slots) ----
        float4* red = (float4*)vs;
        const int base = qg3 * 32 + dg;    // 0..63 (qg3 folded in)

        __syncthreads();
        if (kpart >= 4) {
            int slot = (kpart - 4) * 64 + base;                 // 0..255
            #pragma unroll
            for (int qi = 0; qi < 8; qi++) red[slot + qi * 256] = o[qi];
        }
        __syncthreads();
        if (kpart < 4) {
            int slot = kpart * 64 + base;
            #pragma unroll
            for (int qi = 0; qi < 8; qi++) add4(o[qi], red[slot + qi * 256]);
        }
        __syncthreads();
        if (kpart == 2 || kpart == 3) {
            int slot = (kpart - 2) * 64 + base;                 // 0..127
            #pragma unroll
            for (int qi = 0; qi < 8; qi++) red[slot + qi * 256] = o[qi];
        }
        __syncthreads();
        if (kpart < 2) {
            int slot = kpart * 64 + base;
            #pragma unroll
            for (int qi = 0; qi < 8; qi++) add4(o[qi], red[slot + qi * 256]);
        }
        __syncthreads();
        if (kpart == 1) {
            #pragma unroll
            for (int qi = 0; qi < 8; qi++) red[base + qi * 256] = o[qi];
        }
        __syncthreads();
        if (kpart == 0) {
            #pragma unroll
            for (int qi = 0; qi < 8; qi++) {
                add4(o[qi], red[base + qi * 256]);
                *(float4*)(Ob + (qg3 * 8 + qi) * DDIM + dg * 4) = o[qi];
            }
        }
    }
}

extern "C" void kernel_launch(void* const* d_in, const int* in_sizes, int n_in,
                              void* d_out, int out_size) {
    const float* Q = (const float*)d_in[0];
    const float* K = (const float*)d_in[1];
    const float* V = (const float*)d_in[2];
    float* O = (float*)d_out;

    const int B = in_sizes[0] / (SLEN * DDIM);   // 8
    const size_t smem = (size_t)(TQ * ZSTR + 32 * KSTR2 + 128 * QTSTR) * sizeof(float); // 207,616 B

    cudaFuncSetAttribute(entmax_attn_kernel,
                         cudaFuncAttributeMaxDynamicSharedMemorySize, (int)smem);

    dim3 grid(SLEN / TQ, B);
    entmax_attn_kernel<<<grid, NTHR, smem>>>(Q, K, V, O);
}